// round 1
// baseline (speedup 1.0000x reference)
#include <cuda_runtime.h>

#define B_ 8
#define T_ 4096
#define D_ 256
#define H_ 256
#define G_ 768              // 3H
#define M_ (B_ * T_)        // 32768

// Scratch (static device allocations are allowed; no cudaMalloc anywhere)
__device__ float g_xg[(size_t)2 * B_ * T_ * G_];       // [dir][b][t][768]
__device__ float g_outc[(size_t)B_ * T_ * 2 * H_];     // [b][t][512]  (fwd | bwd)
__device__ unsigned g_bar[2];

__device__ __forceinline__ unsigned ld_acquire(const unsigned* p) {
    unsigned v;
    asm volatile("ld.acquire.gpu.u32 %0, [%1];" : "=r"(v) : "l"(p) : "memory");
    return v;
}

// ---------------------------------------------------------------------------
// Kernel A: xg[d] = X @ Wi_d + bi_d       X:[32768,256] (row = b*T+t), Wi:[256,768]
// Also resets the scan barrier counters (stream-ordered before k_scan).
// ---------------------------------------------------------------------------
__global__ void __launch_bounds__(256) k_xgemm(
    const float* __restrict__ X,
    const float* __restrict__ Wi_f, const float* __restrict__ bi_f,
    const float* __restrict__ Wi_b, const float* __restrict__ bi_b)
{
    if (blockIdx.x == 0 && blockIdx.y == 0 && blockIdx.z == 0 && threadIdx.x == 0) {
        g_bar[0] = 0u; g_bar[1] = 0u;
    }
    const int d = blockIdx.z;
    const float* W  = d ? Wi_b : Wi_f;
    const float* bi = d ? bi_b : bi_f;
    float* out = g_xg + (size_t)d * M_ * G_;

    const int m0 = blockIdx.y * 64;
    const int n0 = blockIdx.x * 64;

    __shared__ float As[16][65];   // [k][m], padded
    __shared__ float Bs[16][64];   // [k][n]

    const int tid = threadIdx.x;
    const int ti = tid >> 4;       // 0..15 -> 4 rows each
    const int tj = tid & 15;       // 0..15 -> 4 cols each

    float acc[4][4];
#pragma unroll
    for (int i = 0; i < 4; ++i)
#pragma unroll
        for (int j = 0; j < 4; ++j) acc[i][j] = 0.f;

    for (int k0 = 0; k0 < D_; k0 += 16) {
#pragma unroll
        for (int p = 0; p < 4; ++p) {
            int idx = tid + p * 256;          // 0..1023
            int r = idx >> 4, c = idx & 15;   // m, k
            As[c][r] = X[(size_t)(m0 + r) * D_ + k0 + c];
        }
#pragma unroll
        for (int p = 0; p < 4; ++p) {
            int idx = tid + p * 256;
            int r = idx >> 6, c = idx & 63;   // k, n
            Bs[r][c] = W[(size_t)(k0 + r) * G_ + n0 + c];
        }
        __syncthreads();
#pragma unroll
        for (int kk = 0; kk < 16; ++kk) {
            float av[4], bv4[4];
#pragma unroll
            for (int i = 0; i < 4; ++i) av[i] = As[kk][ti * 4 + i];
            float4 bq = *(const float4*)&Bs[kk][tj * 4];
            bv4[0] = bq.x; bv4[1] = bq.y; bv4[2] = bq.z; bv4[3] = bq.w;
#pragma unroll
            for (int i = 0; i < 4; ++i)
#pragma unroll
                for (int j = 0; j < 4; ++j)
                    acc[i][j] = fmaf(av[i], bv4[j], acc[i][j]);
        }
        __syncthreads();
    }

#pragma unroll
    for (int j = 0; j < 4; ++j) {
        float bb = bi[n0 + tj * 4 + j];
#pragma unroll
        for (int i = 0; i < 4; ++i) {
            out[(size_t)(m0 + ti * 4 + i) * G_ + n0 + tj * 4 + j] = acc[i][j] + bb;
        }
    }
}

// ---------------------------------------------------------------------------
// Kernel B: persistent bidirectional GRU scan.
// Grid = 128 CTAs: blockIdx.x>>6 = direction, &63 = unit-group (4 hidden units).
// Per step: gh = h @ Wh (slice), GRU elementwise, write h to g_outc, global
// barrier (per direction), reload full h from g_outc.
// ---------------------------------------------------------------------------
__global__ void __launch_bounds__(256) k_scan(
    const float* __restrict__ Wh_f, const float* __restrict__ bhn_f,
    const float* __restrict__ Wh_b, const float* __restrict__ bhn_b)
{
    const int d  = blockIdx.x >> 6;
    const int cg = blockIdx.x & 63;
    const int j0 = cg * 4;
    const float* Wh  = d ? Wh_b  : Wh_f;
    const float* bhn = d ? bhn_b : bhn_f;
    const int dofs = d * H_;

    __shared__ float Wsm[12 * 260];   // 12 gate columns, stride-padded
    __shared__ float hsm[8 * 256];    // full h state, all 8 batches

    const int tid  = threadIdx.x;
    const int warp = tid >> 5;        // warp == batch
    const int lane = tid & 31;

    // Preload Wh columns: c = gate*4 + u -> Wh[:, gate*256 + j0 + u]
    for (int idx = tid; idx < 12 * 256; idx += 256) {
        int c = idx >> 8, k = idx & 255;
        int col = (c >> 2) * H_ + j0 + (c & 3);
        Wsm[c * 260 + k] = Wh[(size_t)k * G_ + col];
    }
    for (int idx = tid; idx < 2048; idx += 256) hsm[idx] = 0.f;  // h0 = 0
    __syncthreads();

    const int b = warp;
    const float bhn_u = (lane < 4) ? bhn[j0 + lane] : 0.f;
    const float* xg_base = g_xg + ((size_t)d * B_ + b) * T_ * G_;

    unsigned target = 0;

    for (int s = 0; s < T_; ++s) {
        const int t = d ? (T_ - 1 - s) : s;

        if (lane < 24) {
            const int seg = (lane >= 12) ? 1 : 0;
            const int c   = lane - seg * 12;       // c = gate*4 + u

            // gi for this (gate,u), issued early to hide DRAM latency
            float giv = 0.f;
            if (lane < 12)
                giv = __ldg(xg_base + (size_t)t * G_ + (c >> 2) * H_ + j0 + (c & 3));

            const float* wp = &Wsm[c * 260 + seg * 128];
            const float* hp = &hsm[b * 256 + seg * 128];
            float a0 = 0.f, a1 = 0.f, a2 = 0.f, a3 = 0.f;
#pragma unroll
            for (int i = 0; i < 128; i += 4) {
                float4 w  = *(const float4*)(wp + i);
                float4 hv = *(const float4*)(hp + i);
                a0 = fmaf(w.x, hv.x, a0);
                a1 = fmaf(w.y, hv.y, a1);
                a2 = fmaf(w.z, hv.z, a2);
                a3 = fmaf(w.w, hv.w, a3);
            }
            float acc = (a0 + a1) + (a2 + a3);
            acc += __shfl_down_sync(0x00FFFFFFu, acc, 12);   // fold seg1 into seg0

            float sum = giv + acc;                 // gi + gh (valid lanes 0..11)
            int u = lane & 3;
            float a_r = __shfl_sync(0x00FFFFFFu, sum, u);
            float a_z = __shfl_sync(0x00FFFFFFu, sum, u + 4);
            float ghn = __shfl_sync(0x00FFFFFFu, acc, u + 8);
            float gin = __shfl_sync(0x00FFFFFFu, giv, u + 8);

            if (lane < 4) {
                float r = 1.f / (1.f + expf(-a_r));
                float z = 1.f / (1.f + expf(-a_z));
                float n = tanhf(fmaf(r, ghn + bhn_u, gin));
                float hprev = hsm[b * 256 + j0 + lane];
                float hn = fmaf(z, hprev - n, n);  // (1-z)*n + z*h
                g_outc[((size_t)b * T_ + t) * (2 * H_) + dofs + j0 + lane] = hn;
            }
        }

        // ---- inter-CTA barrier (per direction) ----
        __threadfence();
        __syncthreads();
        target += 64;
        if (tid == 0) {
            atomicAdd(&g_bar[d], 1u);
            while (ld_acquire(&g_bar[d]) < target) { }
        }
        __syncthreads();

        // reload full h_{s+1} (just written at time t by all 64 CTAs)
        if (s + 1 < T_) {
            for (int i = tid; i < 512; i += 256) {
                int bb = i >> 6, j4 = i & 63;
                const float4* src = (const float4*)
                    &g_outc[((size_t)bb * T_ + t) * (2 * H_) + dofs + j4 * 4];
                float4 v = __ldcg(src);   // L2-fresh, bypass L1
                *(float4*)&hsm[bb * 256 + j4 * 4] = v;
            }
            __syncthreads();
        }
    }
}

// ---------------------------------------------------------------------------
// Kernel C: heads.  out_combined [32768,512] @ (Wm|Wv) [512,256] + bias.
// J = exp(var head) -> d_out[0 : M*H);   h = mean head -> d_out[M*H : 2*M*H).
// ---------------------------------------------------------------------------
__global__ void __launch_bounds__(256) k_heads(
    const float* __restrict__ Wm, const float* __restrict__ bm,
    const float* __restrict__ Wv, const float* __restrict__ bv,
    float* __restrict__ out)
{
    const int n0 = blockIdx.x * 64;        // 0..511 (0..255 mean, 256..511 var)
    const int m0 = blockIdx.y * 64;
    const bool isV = (n0 >= 256);
    const float* W  = isV ? Wv : Wm;       // [512][256]
    const float* bb = isV ? bv : bm;
    const int nw = n0 & 255;

    __shared__ float As[16][65];
    __shared__ float Bs[16][64];

    const int tid = threadIdx.x;
    const int ti = tid >> 4, tj = tid & 15;

    float acc[4][4];
#pragma unroll
    for (int i = 0; i < 4; ++i)
#pragma unroll
        for (int j = 0; j < 4; ++j) acc[i][j] = 0.f;

    for (int k0 = 0; k0 < 512; k0 += 16) {
#pragma unroll
        for (int p = 0; p < 4; ++p) {
            int idx = tid + p * 256;
            int r = idx >> 4, c = idx & 15;
            As[c][r] = g_outc[(size_t)(m0 + r) * 512 + k0 + c];
        }
#pragma unroll
        for (int p = 0; p < 4; ++p) {
            int idx = tid + p * 256;
            int r = idx >> 6, c = idx & 63;
            Bs[r][c] = W[(size_t)(k0 + r) * 256 + nw + c];
        }
        __syncthreads();
#pragma unroll
        for (int kk = 0; kk < 16; ++kk) {
            float av[4], bv4[4];
#pragma unroll
            for (int i = 0; i < 4; ++i) av[i] = As[kk][ti * 4 + i];
            float4 bq = *(const float4*)&Bs[kk][tj * 4];
            bv4[0] = bq.x; bv4[1] = bq.y; bv4[2] = bq.z; bv4[3] = bq.w;
#pragma unroll
            for (int i = 0; i < 4; ++i)
#pragma unroll
                for (int j = 0; j < 4; ++j)
                    acc[i][j] = fmaf(av[i], bv4[j], acc[i][j]);
        }
        __syncthreads();
    }

    const size_t hofs = (size_t)M_ * H_;   // h goes in second half
#pragma unroll
    for (int j = 0; j < 4; ++j) {
        int col = nw + tj * 4 + j;
        float bias = bb[col];
#pragma unroll
        for (int i = 0; i < 4; ++i) {
            int row = m0 + ti * 4 + i;
            float v = acc[i][j] + bias;
            if (isV) out[(size_t)row * 256 + col] = expf(v);     // J_diag
            else     out[hofs + (size_t)row * 256 + col] = v;    // h
        }
    }
}

// ---------------------------------------------------------------------------
extern "C" void kernel_launch(void* const* d_in, const int* in_sizes, int n_in,
                              void* d_out, int out_size)
{
    const float* inputs = (const float*)d_in[0];
    const float* Wi_f   = (const float*)d_in[1];
    const float* bi_f   = (const float*)d_in[2];
    const float* Wh_f   = (const float*)d_in[3];
    const float* bhn_f  = (const float*)d_in[4];
    const float* Wi_b   = (const float*)d_in[5];
    const float* bi_b   = (const float*)d_in[6];
    const float* Wh_b   = (const float*)d_in[7];
    const float* bhn_b  = (const float*)d_in[8];
    const float* Wm     = (const float*)d_in[9];
    const float* bm     = (const float*)d_in[10];
    const float* Wv     = (const float*)d_in[11];
    const float* bv     = (const float*)d_in[12];
    float* out = (float*)d_out;

    (void)in_sizes; (void)n_in; (void)out_size;

    // 1) input projections for both directions (+ barrier reset)
    k_xgemm<<<dim3(12, 512, 2), 256>>>(inputs, Wi_f, bi_f, Wi_b, bi_b);
    // 2) persistent bidirectional scan (64 CTAs per direction, co-resident)
    k_scan<<<128, 256>>>(Wh_f, bhn_f, Wh_b, bhn_b);
    // 3) heads: mean + exp(log-var)
    k_heads<<<dim3(8, 512), 256>>>(Wm, bm, Wv, bv, out);
}

// round 2
// speedup vs baseline: 1.0673x; 1.0673x over previous
#include <cuda_runtime.h>

#define B_ 8
#define T_ 4096
#define D_ 256
#define H_ 256
#define G_ 768              // 3H
#define M_ (B_ * T_)        // 32768

// Scratch (static device allocations are allowed; no cudaMalloc anywhere)
__device__ float g_xg[(size_t)2 * B_ * T_ * G_];       // [dir][b][t][768]
__device__ float g_outc[(size_t)B_ * T_ * 2 * H_];     // [b][t][512]  (fwd | bwd)
__device__ unsigned g_flag[2 * 64 * 32];               // per-CTA epoch, 128B stride

__device__ __forceinline__ unsigned ld_acquire(const unsigned* p) {
    unsigned v;
    asm volatile("ld.acquire.gpu.u32 %0, [%1];" : "=r"(v) : "l"(p) : "memory");
    return v;
}

// ---------------------------------------------------------------------------
// Kernel A: xg[d] = X @ Wi_d + bi_d       X:[32768,256] (row = b*T+t), Wi:[256,768]
// Also resets the scan flag array (stream-ordered before k_scan).
// ---------------------------------------------------------------------------
__global__ void __launch_bounds__(256) k_xgemm(
    const float* __restrict__ X,
    const float* __restrict__ Wi_f, const float* __restrict__ bi_f,
    const float* __restrict__ Wi_b, const float* __restrict__ bi_b)
{
    if (blockIdx.x == 0 && blockIdx.y == 0 && blockIdx.z == 0 && threadIdx.x < 128) {
        g_flag[threadIdx.x * 32] = 0u;
    }
    const int d = blockIdx.z;
    const float* W  = d ? Wi_b : Wi_f;
    const float* bi = d ? bi_b : bi_f;
    float* out = g_xg + (size_t)d * M_ * G_;

    const int m0 = blockIdx.y * 64;
    const int n0 = blockIdx.x * 64;

    __shared__ float As[16][65];   // [k][m], padded
    __shared__ float Bs[16][64];   // [k][n]

    const int tid = threadIdx.x;
    const int ti = tid >> 4;       // 0..15 -> 4 rows each
    const int tj = tid & 15;       // 0..15 -> 4 cols each

    float acc[4][4];
#pragma unroll
    for (int i = 0; i < 4; ++i)
#pragma unroll
        for (int j = 0; j < 4; ++j) acc[i][j] = 0.f;

    for (int k0 = 0; k0 < D_; k0 += 16) {
#pragma unroll
        for (int p = 0; p < 4; ++p) {
            int idx = tid + p * 256;          // 0..1023
            int r = idx >> 4, c = idx & 15;   // m, k
            As[c][r] = X[(size_t)(m0 + r) * D_ + k0 + c];
        }
#pragma unroll
        for (int p = 0; p < 4; ++p) {
            int idx = tid + p * 256;
            int r = idx >> 6, c = idx & 63;   // k, n
            Bs[r][c] = W[(size_t)(k0 + r) * G_ + n0 + c];
        }
        __syncthreads();
#pragma unroll
        for (int kk = 0; kk < 16; ++kk) {
            float av[4], bv4[4];
#pragma unroll
            for (int i = 0; i < 4; ++i) av[i] = As[kk][ti * 4 + i];
            float4 bq = *(const float4*)&Bs[kk][tj * 4];
            bv4[0] = bq.x; bv4[1] = bq.y; bv4[2] = bq.z; bv4[3] = bq.w;
#pragma unroll
            for (int i = 0; i < 4; ++i)
#pragma unroll
                for (int j = 0; j < 4; ++j)
                    acc[i][j] = fmaf(av[i], bv4[j], acc[i][j]);
        }
        __syncthreads();
    }

#pragma unroll
    for (int j = 0; j < 4; ++j) {
        float bb = bi[n0 + tj * 4 + j];
#pragma unroll
        for (int i = 0; i < 4; ++i) {
            out[(size_t)(m0 + ti * 4 + i) * G_ + n0 + tj * 4 + j] = acc[i][j] + bb;
        }
    }
}

// ---------------------------------------------------------------------------
// Kernel B: persistent bidirectional GRU scan.
// 128 CTAs: blockIdx.x>>6 = direction, &63 = unit-group (4 hidden units).
// Per step: gh = h @ Wh slice, GRU elementwise, write h to g_outc,
// distributed flag barrier (per direction), per-warp reload of own batch h.
// ---------------------------------------------------------------------------
__global__ void __launch_bounds__(256) k_scan(
    const float* __restrict__ Wh_f, const float* __restrict__ bhn_f,
    const float* __restrict__ Wh_b, const float* __restrict__ bhn_b)
{
    const int d  = blockIdx.x >> 6;
    const int cg = blockIdx.x & 63;
    const int j0 = cg * 4;
    const float* Wh  = d ? Wh_b  : Wh_f;
    const float* bhn = d ? bhn_b : bhn_f;
    const int dofs = d * H_;

    __shared__ float Wsm[12 * 260];   // 12 gate columns, stride-padded
    __shared__ float hsm[8 * 256];    // full h state, all 8 batches

    const int tid  = threadIdx.x;
    const int warp = tid >> 5;        // warp == batch
    const int lane = tid & 31;

    // Preload Wh columns: c = gate*4 + u -> Wh[:, gate*256 + j0 + u]
    for (int idx = tid; idx < 12 * 256; idx += 256) {
        int c = idx >> 8, k = idx & 255;
        int col = (c >> 2) * H_ + j0 + (c & 3);
        Wsm[c * 260 + k] = Wh[(size_t)k * G_ + col];
    }
    for (int idx = tid; idx < 2048; idx += 256) hsm[idx] = 0.f;  // h0 = 0
    __syncthreads();

    const int b = warp;
    const float bhn_u = (lane < 4) ? bhn[j0 + lane] : 0.f;
    const float* xg_base = g_xg + ((size_t)d * B_ + b) * T_ * G_;
    unsigned* myflag = &g_flag[(d * 64 + cg) * 32];

    // prefetch gi for step 0 (held in register across the step)
    float giv = 0.f;
    {
        const int t0 = d ? (T_ - 1) : 0;
        if (lane < 12)
            giv = __ldg(xg_base + (size_t)t0 * G_ + (lane >> 2) * H_ + j0 + (lane & 3));
    }

    for (int s = 0; s < T_; ++s) {
        const int t = d ? (T_ - 1 - s) : s;

        if (lane < 24) {
            const int seg = (lane >= 12) ? 1 : 0;
            const int c   = lane - seg * 12;       // c = gate*4 + u

            const float* wp = &Wsm[c * 260 + seg * 128];
            const float* hp = &hsm[b * 256 + seg * 128];
            float a0 = 0.f, a1 = 0.f, a2 = 0.f, a3 = 0.f;
#pragma unroll
            for (int i = 0; i < 128; i += 4) {
                float4 w  = *(const float4*)(wp + i);
                float4 hv = *(const float4*)(hp + i);
                a0 = fmaf(w.x, hv.x, a0);
                a1 = fmaf(w.y, hv.y, a1);
                a2 = fmaf(w.z, hv.z, a2);
                a3 = fmaf(w.w, hv.w, a3);
            }
            float acc = (a0 + a1) + (a2 + a3);
            acc += __shfl_down_sync(0x00FFFFFFu, acc, 12);   // fold seg1 into seg0

            float sum = giv + acc;                 // gi + gh (valid lanes 0..11)
            int u = lane & 3;
            float a_r = __shfl_sync(0x00FFFFFFu, sum, u);
            float a_z = __shfl_sync(0x00FFFFFFu, sum, u + 4);
            float ghn = __shfl_sync(0x00FFFFFFu, acc, u + 8);
            float gin = __shfl_sync(0x00FFFFFFu, giv, u + 8);

            if (lane < 4) {
                float r = 1.f / (1.f + expf(-a_r));
                float z = 1.f / (1.f + expf(-a_z));
                float n = tanhf(fmaf(r, ghn + bhn_u, gin));
                float hprev = hsm[b * 256 + j0 + lane];
                float hn = fmaf(z, hprev - n, n);  // (1-z)*n + z*h
                g_outc[((size_t)b * T_ + t) * (2 * H_) + dofs + j0 + lane] = hn;
            }
        }

        __syncthreads();   // all 8 warps' h writes issued

        if (s + 1 < T_) {
            // post our epoch: release-pattern (fence + relaxed store), no atomics
            if (tid == 0) {
                asm volatile("fence.acq_rel.gpu;" ::: "memory");
                asm volatile("st.relaxed.gpu.u32 [%0], %1;"
                             :: "l"(myflag), "r"((unsigned)(s + 1)) : "memory");
            }

            // prefetch gi for step s+1 while we wait (hides HBM/L2 latency)
            float giv_next = 0.f;
            if (lane < 12) {
                const int tn = d ? (T_ - 2 - s) : (s + 1);
                giv_next = __ldg(xg_base + (size_t)tn * G_ + (lane >> 2) * H_ + j0 + (lane & 3));
            }

            // distributed poll: one flag per lane, fully parallel
            if (tid < 64) {
                const unsigned* fp = &g_flag[(d * 64 + tid) * 32];
                while (ld_acquire(fp) <= (unsigned)s) { }
            }
            __syncthreads();

            // per-warp reload of OWN batch h_{s+1} (1KB, 2 x float4 per lane)
            {
                const float4* src = (const float4*)
                    &g_outc[((size_t)b * T_ + t) * (2 * H_) + dofs];
                float4 v0 = __ldcg(src + lane);
                float4 v1 = __ldcg(src + lane + 32);
                *(float4*)&hsm[b * 256 + lane * 4]        = v0;
                *(float4*)&hsm[b * 256 + (lane + 32) * 4] = v1;
            }
            __syncwarp();

            giv = giv_next;
        }
    }
}

// ---------------------------------------------------------------------------
// Kernel C: heads.  out_combined [32768,512] @ (Wm|Wv) [512,256] + bias.
// J = exp(var head) -> d_out[0 : M*H);   h = mean head -> d_out[M*H : 2*M*H).
// ---------------------------------------------------------------------------
__global__ void __launch_bounds__(256) k_heads(
    const float* __restrict__ Wm, const float* __restrict__ bm,
    const float* __restrict__ Wv, const float* __restrict__ bv,
    float* __restrict__ out)
{
    const int n0 = blockIdx.x * 64;        // 0..511 (0..255 mean, 256..511 var)
    const int m0 = blockIdx.y * 64;
    const bool isV = (n0 >= 256);
    const float* W  = isV ? Wv : Wm;       // [512][256]
    const float* bb = isV ? bv : bm;
    const int nw = n0 & 255;

    __shared__ float As[16][65];
    __shared__ float Bs[16][64];

    const int tid = threadIdx.x;
    const int ti = tid >> 4, tj = tid & 15;

    float acc[4][4];
#pragma unroll
    for (int i = 0; i < 4; ++i)
#pragma unroll
        for (int j = 0; j < 4; ++j) acc[i][j] = 0.f;

    for (int k0 = 0; k0 < 512; k0 += 16) {
#pragma unroll
        for (int p = 0; p < 4; ++p) {
            int idx = tid + p * 256;
            int r = idx >> 4, c = idx & 15;
            As[c][r] = g_outc[(size_t)(m0 + r) * 512 + k0 + c];
        }
#pragma unroll
        for (int p = 0; p < 4; ++p) {
            int idx = tid + p * 256;
            int r = idx >> 6, c = idx & 63;
            Bs[r][c] = W[(size_t)(k0 + r) * 256 + nw + c];
        }
        __syncthreads();
#pragma unroll
        for (int kk = 0; kk < 16; ++kk) {
            float av[4], bv4[4];
#pragma unroll
            for (int i = 0; i < 4; ++i) av[i] = As[kk][ti * 4 + i];
            float4 bq = *(const float4*)&Bs[kk][tj * 4];
            bv4[0] = bq.x; bv4[1] = bq.y; bv4[2] = bq.z; bv4[3] = bq.w;
#pragma unroll
            for (int i = 0; i < 4; ++i)
#pragma unroll
                for (int j = 0; j < 4; ++j)
                    acc[i][j] = fmaf(av[i], bv4[j], acc[i][j]);
        }
        __syncthreads();
    }

    const size_t hofs = (size_t)M_ * H_;   // h goes in second half
#pragma unroll
    for (int j = 0; j < 4; ++j) {
        int col = nw + tj * 4 + j;
        float bias = bb[col];
#pragma unroll
        for (int i = 0; i < 4; ++i) {
            int row = m0 + ti * 4 + i;
            float v = acc[i][j] + bias;
            if (isV) out[(size_t)row * 256 + col] = expf(v);     // J_diag
            else     out[hofs + (size_t)row * 256 + col] = v;    // h
        }
    }
}

// ---------------------------------------------------------------------------
extern "C" void kernel_launch(void* const* d_in, const int* in_sizes, int n_in,
                              void* d_out, int out_size)
{
    const float* inputs = (const float*)d_in[0];
    const float* Wi_f   = (const float*)d_in[1];
    const float* bi_f   = (const float*)d_in[2];
    const float* Wh_f   = (const float*)d_in[3];
    const float* bhn_f  = (const float*)d_in[4];
    const float* Wi_b   = (const float*)d_in[5];
    const float* bi_b   = (const float*)d_in[6];
    const float* Wh_b   = (const float*)d_in[7];
    const float* bhn_b  = (const float*)d_in[8];
    const float* Wm     = (const float*)d_in[9];
    const float* bm     = (const float*)d_in[10];
    const float* Wv     = (const float*)d_in[11];
    const float* bv     = (const float*)d_in[12];
    float* out = (float*)d_out;

    (void)in_sizes; (void)n_in; (void)out_size;

    // 1) input projections for both directions (+ flag reset)
    k_xgemm<<<dim3(12, 512, 2), 256>>>(inputs, Wi_f, bi_f, Wi_b, bi_b);
    // 2) persistent bidirectional scan (64 CTAs per direction, co-resident)
    k_scan<<<128, 256>>>(Wh_f, bhn_f, Wh_b, bhn_b);
    // 3) heads: mean + exp(log-var)
    k_heads<<<dim3(8, 512), 256>>>(Wm, bm, Wv, bv, out);
}